// round 9
// baseline (speedup 1.0000x reference)
#include <cuda_runtime.h>
#include <cuda_bf16.h>
#include <mma.h>
#include <cstdint>

using namespace nvcuda;

#define TBG   512
#define TIN   256
#define MROWS 2048      // B*N = 32*64

#define BM    32        // m rows per CTA
#define BI    64        // i cols per CTA
#define LDW   520       // padded leading dim (elements), conflict-free ldmatrix

// smem layout (dynamic):
//   As      : BM x LDW bf16                      [0, 33280)
//   Ws      : BI x LDW bf16 (aliases A staging)  [33280, 99840)
//   q       : 512 float4 (u, e^-bu, e^+bu, 0)    [99840, 108032)
#define AS_BYTES   (BM * LDW * 2)
#define WS_OFF     AS_BYTES
#define WS_BYTES   (BI * LDW * 2)
#define Q_OFF      (WS_OFF + WS_BYTES)
#define SMEM_TOTAL (Q_OFF + TBG * 16)

__device__ __forceinline__ void cp_async16(void* smem_dst, const void* gmem_src) {
    uint32_t a;
    asm("{ .reg .u64 t; cvta.to.shared.u64 t, %1; cvt.u32.u64 %0, t; }"
        : "=r"(a) : "l"(smem_dst));
    asm volatile("cp.async.cg.shared.global [%0], [%1], 16;" :: "r"(a), "l"(gmem_src));
}

__global__ void __launch_bounds__(256, 2)
fused_kernel(const float* __restrict__ surv,
             const float* __restrict__ time_bg,
             const float* __restrict__ time_in,
             const float* __restrict__ bandwidth,
             float* __restrict__ C) {
    extern __shared__ char smem[];
    __nv_bfloat16* As      = reinterpret_cast<__nv_bfloat16*>(smem);
    __nv_bfloat16* Ws      = reinterpret_cast<__nv_bfloat16*>(smem + WS_OFF);
    float*         staging = reinterpret_cast<float*>(smem + WS_OFF);   // alias
    float4*        q       = reinterpret_cast<float4*>(smem + Q_OFF);

    const int tid = threadIdx.x;
    const int wid = tid >> 5;
    const int lid = tid & 31;

    const int i0 = blockIdx.x * BI;   // output col block (T_in)
    const int m0 = blockIdx.y * BM;   // output row block (B*N)

    const float b = fmaxf(bandwidth[0], 1e-6f);

    // ---- 1. cp.async A tile [BM x 512] fp32 -> staging (raw bytes) ----
    {
        const float4* Ag4 = reinterpret_cast<const float4*>(surv + (size_t)m0 * TBG);
        float4* st4 = reinterpret_cast<float4*>(staging);
        #pragma unroll
        for (int it = 0; it < 16; it++) {
            const int idx = it * 256 + tid;     // 4096 chunks of 16B
            cp_async16(&st4[idx], &Ag4[idx]);
        }
        asm volatile("cp.async.commit_group;");
    }

    // ---- 2. exp tables (overlaps the bulk copy) ----
    #pragma unroll
    for (int j = 0; j < 2; j++) {
        const int t = j * 256 + tid;
        const float u = time_bg[t];
        q[t] = make_float4(u, __expf(-b * u), __expf(b * u), 0.0f);
    }

    asm volatile("cp.async.wait_group 0;");
    __syncthreads();

    // ---- 3. convert staging fp32 -> As bf16 (smem -> smem) ----
    {
        const float4* st4 = reinterpret_cast<const float4*>(staging);
        #pragma unroll
        for (int it = 0; it < 16; it++) {
            const int idx = it * 256 + tid;
            const int r   = idx >> 7;          // 0..31
            const int c4  = idx & 127;
            const float4 v = st4[idx];
            __nv_bfloat162 p0 = __floats2bfloat162_rn(v.x, v.y);
            __nv_bfloat162 p1 = __floats2bfloat162_rn(v.z, v.w);
            uint2 o;
            o.x = *reinterpret_cast<unsigned int*>(&p0);
            o.y = *reinterpret_cast<unsigned int*>(&p1);
            *reinterpret_cast<uint2*>(&As[r * LDW + c4 * 4]) = o;
        }
    }
    __syncthreads();   // As done; staging region free for Ws

    // ---- 4. softmin weights, factorized: one exp per i ----
    // raw_t = (u_t >= v) ? e^{-b u_t} : e^{+b u_t} * e^{-2 b v}
    // (common factor e^{b v} cancels in the normalization)
    {
        #pragma unroll 1
        for (int ii = 0; ii < 8; ii++) {
            const int i   = wid * 8 + ii;            // local i 0..63
            const float v = time_in[i0 + i];
            const float g = __expf(-2.0f * b * v);

            float w[16];
            float sm = 0.0f;
            #pragma unroll
            for (int j = 0; j < 16; j++) {
                const float4 qq = q[j * 32 + lid];
                const float raw = (qq.x >= v) ? qq.y : qq.z * g;
                w[j] = raw;
                sm += raw;
            }
            #pragma unroll
            for (int o = 16; o > 0; o >>= 1)
                sm += __shfl_xor_sync(0xffffffffu, sm, o);

            const float inv = __fdividef(1.0f, sm);
            #pragma unroll
            for (int j = 0; j < 16; j++)
                Ws[i * LDW + j * 32 + lid] = __float2bfloat16(w[j] * inv);
        }
    }
    __syncthreads();

    // ---- 5. MMA: warp grid 2(m) x 4(i), warp tile 16m x 16i ----
    {
        const int wm = wid & 1;        // 0..1
        const int wi = wid >> 1;       // 0..3

        wmma::fragment<wmma::accumulator, 16, 16, 16, float> acc;
        wmma::fill_fragment(acc, 0.0f);

        const __nv_bfloat16* a_base = &As[(wm * 16) * LDW];
        const __nv_bfloat16* b_base = &Ws[(wi * 16) * LDW];

        #pragma unroll 8
        for (int kk = 0; kk < TBG; kk += 16) {
            wmma::fragment<wmma::matrix_a, 16, 16, 16, __nv_bfloat16, wmma::row_major> af;
            wmma::fragment<wmma::matrix_b, 16, 16, 16, __nv_bfloat16, wmma::col_major> bf;
            wmma::load_matrix_sync(af, a_base + kk, LDW);
            wmma::load_matrix_sync(bf, b_base + kk, LDW);
            wmma::mma_sync(acc, af, bf, acc);
        }

        float* cp = C + (size_t)(m0 + wm * 16) * TIN + i0 + wi * 16;
        wmma::store_matrix_sync(cp, acc, TIN, wmma::mem_row_major);
    }
}

// ===========================================================================
extern "C" void kernel_launch(void* const* d_in, const int* in_sizes, int n_in,
                              void* d_out, int out_size) {
    const float* surv      = (const float*)d_in[0];
    const float* time_bg   = (const float*)d_in[1];
    const float* time_in   = (const float*)d_in[2];
    const float* bandwidth = (const float*)d_in[3];
    float*       out       = (float*)d_out;

    static bool attr_done = false;
    if (!attr_done) {
        cudaFuncSetAttribute(fused_kernel,
                             cudaFuncAttributeMaxDynamicSharedMemorySize, SMEM_TOTAL);
        attr_done = true;
    }

    dim3 grid(TIN / BI, MROWS / BM);   // (4, 64) = 256 CTAs, 2 per SM
    fused_kernel<<<grid, 256, SMEM_TOTAL>>>(surv, time_bg, time_in, bandwidth, out);
}

// round 11
// speedup vs baseline: 1.3434x; 1.3434x over previous
#include <cuda_runtime.h>
#include <cuda_bf16.h>
#include <mma.h>
#include <cstdint>

using namespace nvcuda;

#define TBG   512
#define TIN   256
#define MROWS 2048      // B*N = 32*64

#define LDW   520       // padded bf16 leading dim (1040B rows, conflict-free)
#define LDP   72        // padded f32 leading dim for partial tile

// smem layout (dynamic):
//   As : 64 x LDW bf16                    [0, 66560)
//   Ws : 64 x LDW bf16                    [66560, 133120)
//   q  : 512 float4 (u, e^-bu, e^+bu, 0)  [133120, 141312)
//   Ps : 64 x LDP f32 (k-split partials)  [141312, 159744)
#define AS_BYTES   (64 * LDW * 2)
#define WS_OFF     AS_BYTES
#define Q_OFF      (2 * AS_BYTES)
#define P_OFF      (Q_OFF + TBG * 16)
#define SMEM_TOTAL (P_OFF + 64 * LDP * 4)

__global__ void __launch_bounds__(512, 1)
fused_kernel(const float* __restrict__ surv,
             const float* __restrict__ time_bg,
             const float* __restrict__ time_in,
             const float* __restrict__ bandwidth,
             float* __restrict__ C) {
    extern __shared__ char smem[];
    __nv_bfloat16* As = reinterpret_cast<__nv_bfloat16*>(smem);
    __nv_bfloat16* Ws = reinterpret_cast<__nv_bfloat16*>(smem + WS_OFF);
    float4*        q  = reinterpret_cast<float4*>(smem + Q_OFF);
    float*         Ps = reinterpret_cast<float*>(smem + P_OFF);

    const int tid = threadIdx.x;
    const int wid = tid >> 5;
    const int lid = tid & 31;

    const int i0 = blockIdx.x * 64;   // output col block (T_in)
    const int m0 = blockIdx.y * 64;   // output row block (B*N)

    const float b = fmaxf(bandwidth[0], 1e-6f);

    // ---- 1. exp table: one t per thread (2 MUFU each) ----
    {
        const float u = time_bg[tid];
        q[tid] = make_float4(u, __expf(-b * u), __expf(b * u), 0.0f);
    }

    // ---- 2. A tile [64 x 512] fp32 -> bf16 smem (16 float4 / thread) ----
    {
        const float* Ag = surv + (size_t)m0 * TBG;
        #pragma unroll
        for (int it = 0; it < 16; it++) {
            const int idx = it * 512 + tid;    // 8192 float4 total
            const int r   = idx >> 7;          // 0..63
            const int c4  = idx & 127;
            const float4 v = *reinterpret_cast<const float4*>(Ag + (size_t)r * TBG + c4 * 4);
            __nv_bfloat162 p0 = __floats2bfloat162_rn(v.x, v.y);
            __nv_bfloat162 p1 = __floats2bfloat162_rn(v.z, v.w);
            uint2 o;
            o.x = *reinterpret_cast<unsigned int*>(&p0);
            o.y = *reinterpret_cast<unsigned int*>(&p1);
            *reinterpret_cast<uint2*>(&As[r * LDW + c4 * 4]) = o;
        }
    }
    __syncthreads();   // q + As ready

    // ---- 3. softmin weights, factorized (one exp per i): 4 i's / warp ----
    // raw_t = (u_t >= v) ? e^{-b u_t} : e^{+b u_t} * e^{-2 b v}
    {
        #pragma unroll 1
        for (int ii = 0; ii < 4; ii++) {
            const int i   = wid * 4 + ii;            // local i 0..63
            const float v = time_in[i0 + i];
            const float g = __expf(-2.0f * b * v);

            float w[16];
            float sm = 0.0f;
            #pragma unroll
            for (int j = 0; j < 16; j++) {
                const float4 qq = q[j * 32 + lid];
                const float raw = (qq.x >= v) ? qq.y : qq.z * g;
                w[j] = raw;
                sm += raw;
            }
            #pragma unroll
            for (int o = 16; o > 0; o >>= 1)
                sm += __shfl_xor_sync(0xffffffffu, sm, o);

            const float inv = __fdividef(1.0f, sm);
            #pragma unroll
            for (int j = 0; j < 16; j++)
                Ws[i * LDW + j * 32 + lid] = __float2bfloat16(w[j] * inv);
        }
    }
    __syncthreads();

    // ---- 4. MMA with K-split x2: warps 0-7 -> k[0,256), 8-15 -> k[256,512)
    //         per half: warp grid 2m x 4i, warp tile 32m x 16i (2 frags)
    const int wk = wid >> 3;         // 0..1 (k half)
    const int w8 = wid & 7;
    const int wm = w8 >> 2;          // 0..1
    const int wi = w8 & 3;           // 0..3

    wmma::fragment<wmma::accumulator, 16, 16, 16, float> acc[2];
    wmma::fill_fragment(acc[0], 0.0f);
    wmma::fill_fragment(acc[1], 0.0f);

    {
        const __nv_bfloat16* a_base = &As[(wm * 32) * LDW + wk * 256];
        const __nv_bfloat16* b_base = &Ws[(wi * 16) * LDW + wk * 256];

        #pragma unroll 8
        for (int kk = 0; kk < 256; kk += 16) {
            wmma::fragment<wmma::matrix_a, 16, 16, 16, __nv_bfloat16, wmma::row_major> af0, af1;
            wmma::fragment<wmma::matrix_b, 16, 16, 16, __nv_bfloat16, wmma::col_major> bf;
            wmma::load_matrix_sync(af0, a_base + kk, LDW);
            wmma::load_matrix_sync(af1, a_base + 16 * LDW + kk, LDW);
            wmma::load_matrix_sync(bf,  b_base + kk, LDW);
            wmma::mma_sync(acc[0], af0, bf, acc[0]);
            wmma::mma_sync(acc[1], af1, bf, acc[1]);
        }
    }

    // ---- 5. reduce the two K halves, store C ----
    __syncthreads();     // As/Ws reads done (Ps does not alias, but order warps)
    if (wk == 1) {
        wmma::store_matrix_sync(&Ps[(wm * 32)      * LDP + wi * 16], acc[0], LDP, wmma::mem_row_major);
        wmma::store_matrix_sync(&Ps[(wm * 32 + 16) * LDP + wi * 16], acc[1], LDP, wmma::mem_row_major);
    }
    __syncthreads();
    if (wk == 0) {
        wmma::fragment<wmma::accumulator, 16, 16, 16, float> pf;

        wmma::load_matrix_sync(pf, &Ps[(wm * 32) * LDP + wi * 16], LDP, wmma::mem_row_major);
        #pragma unroll
        for (int t = 0; t < pf.num_elements; t++) acc[0].x[t] += pf.x[t];

        wmma::load_matrix_sync(pf, &Ps[(wm * 32 + 16) * LDP + wi * 16], LDP, wmma::mem_row_major);
        #pragma unroll
        for (int t = 0; t < pf.num_elements; t++) acc[1].x[t] += pf.x[t];

        float* cp0 = C + (size_t)(m0 + wm * 32)      * TIN + i0 + wi * 16;
        float* cp1 = C + (size_t)(m0 + wm * 32 + 16) * TIN + i0 + wi * 16;
        wmma::store_matrix_sync(cp0, acc[0], TIN, wmma::mem_row_major);
        wmma::store_matrix_sync(cp1, acc[1], TIN, wmma::mem_row_major);
    }
}

// ===========================================================================
extern "C" void kernel_launch(void* const* d_in, const int* in_sizes, int n_in,
                              void* d_out, int out_size) {
    const float* surv      = (const float*)d_in[0];
    const float* time_bg   = (const float*)d_in[1];
    const float* time_in   = (const float*)d_in[2];
    const float* bandwidth = (const float*)d_in[3];
    float*       out       = (float*)d_out;

    static bool attr_done = false;
    if (!attr_done) {
        cudaFuncSetAttribute(fused_kernel,
                             cudaFuncAttributeMaxDynamicSharedMemorySize, SMEM_TOTAL);
        attr_done = true;
    }

    dim3 grid(TIN / 64, MROWS / 64);   // (4, 32) = 128 CTAs
    fused_kernel<<<grid, 512, SMEM_TOTAL>>>(surv, time_bg, time_in, bandwidth, out);
}